// round 3
// baseline (speedup 1.0000x reference)
#include <cuda_runtime.h>
#include <math.h>

// Problem constants
#define TT 65536
#define DD 256
#define LL 3

// GEMM tiling
#define BM 128
#define BN 64
#define KT 16
#define XP (BM + 4)   // padded smem row for x/q tiles

// Scan blocking
#define CS 256
#define NB (TT / CS)  // 256

// ---------------------------------------------------------------------------
// Scratch (device globals; no runtime allocation allowed)
// ---------------------------------------------------------------------------
__device__ float g_q[TT * DD];     // current-layer question per step
__device__ float g_af[TT * DD];    // forward: a -> Aprefix (in place after scan1)
__device__ float g_bf[TT * DD];    // forward: b -> h_local
__device__ float g_ab[TT * DD];    // backward: a -> Aprefix
__device__ float g_bb[TT * DD];    // backward: b -> h_local
__device__ float g_aggA_f[NB * DD];
__device__ float g_aggB_f[NB * DD];
__device__ float g_hex_f[NB * DD];
__device__ float g_aggA_b[NB * DD];
__device__ float g_aggB_b[NB * DD];
__device__ float g_hex_b[NB * DD];

__device__ __forceinline__ float tanh_fast(float v) {
    float r;
    asm("tanh.approx.f32 %0, %1;" : "=f"(r) : "f"(v));
    return r;
}

// ---------------------------------------------------------------------------
// Fused GEMM + activation kernel.
// Computes, for rows t in this M-block and cols d in this N-block:
//   z  = sigmoid( (x*q) @ Wz + bz )
//   ht = tanh( x @ Wh[0:D] + q @ Wh[D:2D] + bh )
//   outA = 1 - z           (multiplicative scan coefficient)
//   outB = z * ht          (additive scan term)
// rev=1 maps row r -> story row (TT-1-r) (backward direction).
// qstride=0 broadcasts the layer-0 question vector.
// ---------------------------------------------------------------------------
__global__ void __launch_bounds__(256, 1) gemm_act_kernel(
    const float* __restrict__ x, const float* __restrict__ qp, int qstride, int rev,
    const float* __restrict__ Wz, const float* __restrict__ bz,
    const float* __restrict__ Wh, const float* __restrict__ bh,
    float* __restrict__ outA, float* __restrict__ outB)
{
    extern __shared__ float sm[];
    float* Wz_s  = sm;                    // [256][64]
    float* Whx_s = Wz_s  + 256 * BN;      // [256][64]
    float* Whq_s = Whx_s + 256 * BN;      // [256][64]
    float* xs    = Whq_s + 256 * BN;      // [KT][XP]
    float* qs    = xs + KT * XP;          // [KT][XP]

    const int tid = threadIdx.x;
    const int tx = tid & 15;              // N micro (4 cols)
    const int ty = tid >> 4;              // M micro (8 rows)
    const int nbase = blockIdx.y * BN;
    const int tbase = blockIdx.x * BM;

    // Load the whole weight N-slice into smem (K resident for full loop)
    #pragma unroll
    for (int it = 0; it < 16; ++it) {
        int j = tid + it * 256;
        int k = j >> 4;
        int c = (j & 15) << 2;
        *(float4*)(Wz_s  + k * BN + c) = *(const float4*)(Wz + k * DD + nbase + c);
        *(float4*)(Whx_s + k * BN + c) = *(const float4*)(Wh + k * DD + nbase + c);
        *(float4*)(Whq_s + k * BN + c) = *(const float4*)(Wh + (k + DD) * DD + nbase + c);
    }

    float accz[8][4], acch[8][4];
    #pragma unroll
    for (int i = 0; i < 8; ++i)
        #pragma unroll
        for (int j = 0; j < 4; ++j) { accz[i][j] = 0.f; acch[i][j] = 0.f; }

    // tile load lambdas: 512 float4 per array per tile, 2 per thread
    auto loadtile = [&](int kk, float4* px, float4* pq) {
        #pragma unroll
        for (int it = 0; it < 2; ++it) {
            int j = tid + it * 256;
            int r = j >> 2;
            int cc = (j & 3) << 2;
            int tg = rev ? (TT - 1 - (tbase + r)) : (tbase + r);
            px[it] = *(const float4*)(x + tg * DD + kk + cc);
            pq[it] = *(const float4*)(qp + tg * qstride + kk + cc);
        }
    };
    auto storetile = [&](const float4* px, const float4* pq) {
        #pragma unroll
        for (int it = 0; it < 2; ++it) {
            int j = tid + it * 256;
            int r = j >> 2;
            int cc = (j & 3) << 2;
            xs[(cc + 0) * XP + r] = px[it].x;
            xs[(cc + 1) * XP + r] = px[it].y;
            xs[(cc + 2) * XP + r] = px[it].z;
            xs[(cc + 3) * XP + r] = px[it].w;
            qs[(cc + 0) * XP + r] = pq[it].x;
            qs[(cc + 1) * XP + r] = pq[it].y;
            qs[(cc + 2) * XP + r] = pq[it].z;
            qs[(cc + 3) * XP + r] = pq[it].w;
        }
    };

    float4 px[2], pq[2];
    loadtile(0, px, pq);
    storetile(px, pq);
    __syncthreads();

    #pragma unroll 1
    for (int kt = 0; kt < 256 / KT; ++kt) {
        const int kk = kt * KT;
        if (kt < 256 / KT - 1) loadtile(kk + KT, px, pq);  // prefetch to regs

        #pragma unroll
        for (int k = 0; k < KT; ++k) {
            float xv[8], qv[8];
            *(float4*)(xv)     = *(const float4*)(xs + k * XP + ty * 8);
            *(float4*)(xv + 4) = *(const float4*)(xs + k * XP + ty * 8 + 4);
            *(float4*)(qv)     = *(const float4*)(qs + k * XP + ty * 8);
            *(float4*)(qv + 4) = *(const float4*)(qs + k * XP + ty * 8 + 4);
            float4 wz = *(const float4*)(Wz_s  + (kk + k) * BN + tx * 4);
            float4 wx = *(const float4*)(Whx_s + (kk + k) * BN + tx * 4);
            float4 wq = *(const float4*)(Whq_s + (kk + k) * BN + tx * 4);
            #pragma unroll
            for (int i = 0; i < 8; ++i) {
                float u = xv[i] * qv[i];
                accz[i][0] = fmaf(u, wz.x, accz[i][0]);
                accz[i][1] = fmaf(u, wz.y, accz[i][1]);
                accz[i][2] = fmaf(u, wz.z, accz[i][2]);
                accz[i][3] = fmaf(u, wz.w, accz[i][3]);
                acch[i][0] = fmaf(xv[i], wx.x, acch[i][0]);
                acch[i][1] = fmaf(xv[i], wx.y, acch[i][1]);
                acch[i][2] = fmaf(xv[i], wx.z, acch[i][2]);
                acch[i][3] = fmaf(xv[i], wx.w, acch[i][3]);
                acch[i][0] = fmaf(qv[i], wq.x, acch[i][0]);
                acch[i][1] = fmaf(qv[i], wq.y, acch[i][1]);
                acch[i][2] = fmaf(qv[i], wq.z, acch[i][2]);
                acch[i][3] = fmaf(qv[i], wq.w, acch[i][3]);
            }
        }
        __syncthreads();
        if (kt < 256 / KT - 1) { storetile(px, pq); __syncthreads(); }
    }

    // Epilogue: activations -> (a, b)
    float4 bzv = *(const float4*)(bz + nbase + tx * 4);
    float4 bhv = *(const float4*)(bh + nbase + tx * 4);
    const float* bzp = (const float*)&bzv;
    const float* bhp = (const float*)&bhv;
    #pragma unroll
    for (int i = 0; i < 8; ++i) {
        int t = tbase + ty * 8 + i;
        float4 av, bv;
        float* pa = (float*)&av;
        float* pb = (float*)&bv;
        #pragma unroll
        for (int j = 0; j < 4; ++j) {
            float zz = accz[i][j] + bzp[j];
            float z = 0.5f * tanh_fast(0.5f * zz) + 0.5f;  // sigmoid
            float th = tanh_fast(acch[i][j] + bhp[j]);
            pa[j] = 1.f - z;
            pb[j] = z * th;
        }
        *(float4*)(outA + t * DD + nbase + tx * 4) = av;
        *(float4*)(outB + t * DD + nbase + tx * 4) = bv;
    }
}

// ---------------------------------------------------------------------------
// scan1: block-local scan over CS timesteps per CTA, one channel per thread.
// In place: A[t] -> running product of a within block (Aprefix),
//           B[t] -> local hidden with h0=0 (h_local).
// Emits per-block aggregate (A,B).
// ---------------------------------------------------------------------------
__global__ void scan1_kernel(float* __restrict__ A, float* __restrict__ B,
                             float* __restrict__ aggA, float* __restrict__ aggB)
{
    const int d = threadIdx.x;
    const int base = blockIdx.x * CS * DD + d;
    float Ap = 1.f, hl = 0.f;
    for (int i0 = 0; i0 < CS; i0 += 8) {
        float a[8], bb[8];
        #pragma unroll
        for (int i = 0; i < 8; ++i) {
            a[i]  = A[base + (i0 + i) * DD];
            bb[i] = B[base + (i0 + i) * DD];
        }
        #pragma unroll
        for (int i = 0; i < 8; ++i) {
            Ap *= a[i];
            hl = fmaf(a[i], hl, bb[i]);
            a[i] = Ap;
            bb[i] = hl;
        }
        #pragma unroll
        for (int i = 0; i < 8; ++i) {
            A[base + (i0 + i) * DD] = a[i];
            B[base + (i0 + i) * DD] = bb[i];
        }
    }
    aggA[blockIdx.x * DD + d] = Ap;
    aggB[blockIdx.x * DD + d] = hl;
}

// ---------------------------------------------------------------------------
// scan2: exclusive scan over block aggregates. hex[b] = hidden state entering
// block b. One CTA, one channel per thread, sequential over NB blocks.
// ---------------------------------------------------------------------------
__global__ void scan2_kernel(const float* __restrict__ aggA,
                             const float* __restrict__ aggB,
                             float* __restrict__ hex)
{
    const int d = threadIdx.x;
    float H = 0.f;
    for (int b = 0; b < NB; ++b) {
        hex[b * DD + d] = H;
        H = fmaf(aggA[b * DD + d], H, aggB[b * DD + d]);
    }
}

// ---------------------------------------------------------------------------
// combine: q_next[t] = h_fwd[t] + h_bwd_rev[T-1-t], with cross-block fixup
// applied on the fly: h[t] = Aprefix[t] * hex[block(t)] + h_local[t].
// ---------------------------------------------------------------------------
__global__ void combine_kernel(
    const float* __restrict__ Af, const float* __restrict__ Bf,
    const float* __restrict__ hexf,
    const float* __restrict__ Ab, const float* __restrict__ Bb,
    const float* __restrict__ hexb,
    float* __restrict__ qout)
{
    int idx = blockIdx.x * blockDim.x + threadIdx.x;   // float4 index
    int t = idx >> 6;            // 64 float4 per row
    int c = (idx & 63) << 2;     // channel base
    int tr = TT - 1 - t;
    int blf = t >> 8;            // CS = 256
    int blb = tr >> 8;

    float4 af = *(const float4*)(Af + t * DD + c);
    float4 bf = *(const float4*)(Bf + t * DD + c);
    float4 hf = *(const float4*)(hexf + blf * DD + c);
    float4 ab = *(const float4*)(Ab + tr * DD + c);
    float4 bb = *(const float4*)(Bb + tr * DD + c);
    float4 hb = *(const float4*)(hexb + blb * DD + c);

    float4 o;
    o.x = fmaf(af.x, hf.x, bf.x) + fmaf(ab.x, hb.x, bb.x);
    o.y = fmaf(af.y, hf.y, bf.y) + fmaf(ab.y, hb.y, bb.y);
    o.z = fmaf(af.z, hf.z, bf.z) + fmaf(ab.z, hb.z, bb.z);
    o.w = fmaf(af.w, hf.w, bf.w) + fmaf(ab.w, hb.w, bb.w);
    *(float4*)(qout + t * DD + c) = o;
}

// final output: h_fwd[T-1] of last layer
__global__ void final_kernel(const float* __restrict__ Af,
                             const float* __restrict__ Bf,
                             const float* __restrict__ hexf,
                             float* __restrict__ out)
{
    const int d = threadIdx.x;
    out[d] = fmaf(Af[(TT - 1) * DD + d], hexf[(NB - 1) * DD + d],
                  Bf[(TT - 1) * DD + d]);
}

// ---------------------------------------------------------------------------
// Host orchestration
// ---------------------------------------------------------------------------
extern "C" void kernel_launch(void* const* d_in, const int* in_sizes, int n_in,
                              void* d_out, int out_size)
{
    const float* story    = (const float*)d_in[0];
    const float* question = (const float*)d_in[1];
    const float* Wz_f = (const float*)d_in[2];
    const float* bz_f = (const float*)d_in[3];
    const float* Wh_f = (const float*)d_in[4];
    const float* bh_f = (const float*)d_in[5];
    const float* Wz_b = (const float*)d_in[6];
    const float* bz_b = (const float*)d_in[7];
    const float* Wh_b = (const float*)d_in[8];
    const float* bh_b = (const float*)d_in[9];
    float* out = (float*)d_out;

    float *qbuf, *af, *bf, *ab, *bb;
    float *aggAf, *aggBf, *hexf, *aggAb, *aggBb, *hexb;
    cudaGetSymbolAddress((void**)&qbuf,  g_q);
    cudaGetSymbolAddress((void**)&af,    g_af);
    cudaGetSymbolAddress((void**)&bf,    g_bf);
    cudaGetSymbolAddress((void**)&ab,    g_ab);
    cudaGetSymbolAddress((void**)&bb,    g_bb);
    cudaGetSymbolAddress((void**)&aggAf, g_aggA_f);
    cudaGetSymbolAddress((void**)&aggBf, g_aggB_f);
    cudaGetSymbolAddress((void**)&hexf,  g_hex_f);
    cudaGetSymbolAddress((void**)&aggAb, g_aggA_b);
    cudaGetSymbolAddress((void**)&aggBb, g_aggB_b);
    cudaGetSymbolAddress((void**)&hexb,  g_hex_b);

    const int SMEM_BYTES = (3 * 256 * BN + 2 * KT * XP) * (int)sizeof(float);
    cudaFuncSetAttribute(gemm_act_kernel,
                         cudaFuncAttributeMaxDynamicSharedMemorySize, SMEM_BYTES);

    dim3 ggrid(TT / BM, DD / BN);

    for (int l = 0; l < LL; ++l) {
        const float* qp = (l == 0) ? question : qbuf;
        int qstride = (l == 0) ? 0 : DD;

        // forward direction
        gemm_act_kernel<<<ggrid, 256, SMEM_BYTES>>>(
            story, qp, qstride, 0,
            Wz_f + l * DD * DD, bz_f + l * DD,
            Wh_f + l * 2 * DD * DD, bh_f + l * DD, af, bf);
        scan1_kernel<<<NB, 256>>>(af, bf, aggAf, aggBf);
        scan2_kernel<<<1, 256>>>(aggAf, aggBf, hexf);

        if (l < LL - 1) {
            // backward direction (skipped for last layer: h_bwd unused)
            gemm_act_kernel<<<ggrid, 256, SMEM_BYTES>>>(
                story, qp, qstride, 1,
                Wz_b + l * DD * DD, bz_b + l * DD,
                Wh_b + l * 2 * DD * DD, bh_b + l * DD, ab, bb);
            scan1_kernel<<<NB, 256>>>(ab, bb, aggAb, aggBb);
            scan2_kernel<<<1, 256>>>(aggAb, aggBb, hexb);

            combine_kernel<<<TT * DD / 4 / 256, 256>>>(
                af, bf, hexf, ab, bb, hexb, qbuf);
        } else {
            final_kernel<<<1, 256>>>(af, bf, hexf, out);
        }
    }
}

// round 5
// speedup vs baseline: 1.7519x; 1.7519x over previous
#include <cuda_runtime.h>
#include <cuda_bf16.h>
#include <stdint.h>
#include <math.h>

// Problem constants
#define TT 65536
#define DD 256
#define LL 3

// GEMM tiling (mma.sync version)
#define BM 128        // timesteps per CTA
#define BN 64         // output channels per CTA
#define KC 32         // K chunk
#define NCHUNK (DD / KC)  // 8

#define ROWB 80       // padded smem row stride (bytes) for bf16 tiles
#define A_TILE (128 * ROWB)          // 10240 B
#define B_TILE (64 * ROWB)           // 5120 B
#define BUFSZ  (6 * A_TILE + 6 * B_TILE)  // 92160 B
#define SM_BIAS (2 * BUFSZ)          // 184320
#define SMEM_TOTAL (SM_BIAS + 512 + 64)

// Scan blocking
#define CS 256
#define NB (TT / CS)  // 256

// ---------------------------------------------------------------------------
// Scratch (device globals; no runtime allocation allowed)
// ---------------------------------------------------------------------------
__device__ __align__(256) float g_q[TT * DD];
__device__ __align__(256) float g_af[TT * DD];
__device__ __align__(256) float g_bf[TT * DD];
__device__ __align__(256) float g_ab[TT * DD];
__device__ __align__(256) float g_bb[TT * DD];
__device__ __align__(256) float g_aggA_f[NB * DD];
__device__ __align__(256) float g_aggB_f[NB * DD];
__device__ __align__(256) float g_hex_f[NB * DD];
__device__ __align__(256) float g_aggA_b[NB * DD];
__device__ __align__(256) float g_aggB_b[NB * DD];
__device__ __align__(256) float g_hex_b[NB * DD];
// pre-transposed, hi/lo-split weights: [5 layer-dirs][3 mats][256 n][256 k]
__device__ __align__(256) __nv_bfloat16 g_whi[5 * 3 * DD * DD];
__device__ __align__(256) __nv_bfloat16 g_wlo[5 * 3 * DD * DD];

__device__ __forceinline__ float tanh_fast(float v) {
    float r;
    asm("tanh.approx.f32 %0, %1;" : "=f"(r) : "f"(v));
    return r;
}

__device__ __forceinline__ uint32_t smem_u32(const void* p) {
    uint32_t a;
    asm("{ .reg .u64 t; cvta.to.shared.u64 t, %1; cvt.u32.u64 %0, t; }"
        : "=r"(a) : "l"(p));
    return a;
}

__device__ __forceinline__ void ldsm4(uint32_t addr, uint32_t* r) {
    asm volatile("ldmatrix.sync.aligned.m8n8.x4.shared.b16 {%0,%1,%2,%3}, [%4];"
                 : "=r"(r[0]), "=r"(r[1]), "=r"(r[2]), "=r"(r[3]) : "r"(addr));
}

__device__ __forceinline__ void mma16816(float* c, const uint32_t* a,
                                         const uint32_t* b) {
    asm volatile(
        "mma.sync.aligned.m16n8k16.row.col.f32.bf16.bf16.f32 "
        "{%0,%1,%2,%3}, {%4,%5,%6,%7}, {%8,%9}, {%0,%1,%2,%3};"
        : "+f"(c[0]), "+f"(c[1]), "+f"(c[2]), "+f"(c[3])
        : "r"(a[0]), "r"(a[1]), "r"(a[2]), "r"(a[3]), "r"(b[0]), "r"(b[1]));
}

// hi/lo bf16 split of a float4; 8B store each
__device__ __forceinline__ void split_store(float4 v, char* hi, char* lo) {
    __nv_bfloat16 h0 = __float2bfloat16_rn(v.x);
    __nv_bfloat16 h1 = __float2bfloat16_rn(v.y);
    __nv_bfloat16 h2 = __float2bfloat16_rn(v.z);
    __nv_bfloat16 h3 = __float2bfloat16_rn(v.w);
    __nv_bfloat162 H0; H0.x = h0; H0.y = h1;
    __nv_bfloat162 H1; H1.x = h2; H1.y = h3;
    __nv_bfloat162 L0, L1;
    L0.x = __float2bfloat16_rn(v.x - __bfloat162float(h0));
    L0.y = __float2bfloat16_rn(v.y - __bfloat162float(h1));
    L1.x = __float2bfloat16_rn(v.z - __bfloat162float(h2));
    L1.y = __float2bfloat16_rn(v.w - __bfloat162float(h3));
    uint2 H; H.x = *(uint32_t*)&H0; H.y = *(uint32_t*)&H1;
    uint2 L; L.x = *(uint32_t*)&L0; L.y = *(uint32_t*)&L1;
    *(uint2*)hi = H;
    *(uint2*)lo = L;
}

// ---------------------------------------------------------------------------
// Weight preprocessing: transpose to [n][k] and split into hi/lo bf16.
// ---------------------------------------------------------------------------
__global__ void prep_weights(const float* __restrict__ Wz,
                             const float* __restrict__ Wh,
                             __nv_bfloat16* __restrict__ whi,
                             __nv_bfloat16* __restrict__ wlo) {
    int n = blockIdx.x, m = blockIdx.y, k = threadIdx.x;
    float v = (m == 0) ? Wz[k * DD + n]
            : (m == 1) ? Wh[k * DD + n]
                       : Wh[(DD + k) * DD + n];
    __nv_bfloat16 hi = __float2bfloat16_rn(v);
    __nv_bfloat16 lo = __float2bfloat16_rn(v - __bfloat162float(hi));
    whi[(m * DD + n) * DD + k] = hi;
    wlo[(m * DD + n) * DD + k] = lo;
}

// ---------------------------------------------------------------------------
// Fused GEMM (mma.sync bf16, 3-pass hi/lo split) + activation kernel.
//   z-pre = (x*q) @ Wz ;  h-pre = x @ Whx + q @ Whq
//   outA = 1 - sigmoid(z-pre + bz) ; outB = sigmoid(..) * tanh(h-pre + bh)
// ---------------------------------------------------------------------------
__global__ void __launch_bounds__(256, 1) gemm_mma(
    const float* __restrict__ x, const float* __restrict__ qp, int qstride, int rev,
    const __nv_bfloat16* __restrict__ whi, const __nv_bfloat16* __restrict__ wlo,
    const float* __restrict__ bz, const float* __restrict__ bh,
    float* __restrict__ outA, float* __restrict__ outB)
{
    extern __shared__ char smem[];
    const int tid = threadIdx.x;
    const int wid = tid >> 5;
    const int lane = tid & 31;
    const int wm = wid & 3;        // warp M index (rows wm*32..+31)
    const int wn = wid >> 2;       // warp N index (cols wn*32..+31)
    const int tbase = blockIdx.x * BM;
    const int nbase = blockIdx.y * BN;
    const uint32_t sb = smem_u32(smem);

    float* bzs = (float*)(smem + SM_BIAS);
    float* bhs = bzs + 64;
    if (tid < 64) {
        bzs[tid] = bz[nbase + tid];
        bhs[tid] = bh[nbase + tid];
    }

    // weight source pointers: Wz hi/lo, Whx hi/lo, Whq hi/lo
    const __nv_bfloat16* w6[6] = {
        whi, wlo, whi + DD * DD, wlo + DD * DD, whi + 2 * DD * DD, wlo + 2 * DD * DD
    };

    // accumulators: [z=0/h=1][mt][nt][4]
    float acc[2][2][4][4];
    #pragma unroll
    for (int zh = 0; zh < 2; ++zh)
        #pragma unroll
        for (int mt = 0; mt < 2; ++mt)
            #pragma unroll
            for (int nt = 0; nt < 4; ++nt)
                #pragma unroll
                for (int j = 0; j < 4; ++j) acc[zh][mt][nt][j] = 0.f;

    // --- staging helpers ---------------------------------------------------
    float4 pxv[4], pqv[4];
    auto load_xq = [&](int k0) {
        #pragma unroll
        for (int it = 0; it < 4; ++it) {
            int j = tid + it * 256;
            int m = j >> 3, kq = j & 7;
            int tg = rev ? (TT - 1 - (tbase + m)) : (tbase + m);
            pxv[it] = *(const float4*)(x + (size_t)tg * DD + k0 + kq * 4);
            pqv[it] = *(const float4*)(qp + (size_t)tg * qstride + k0 + kq * 4);
        }
    };
    auto stage_A = [&](int buf) {
        char* base = smem + buf * BUFSZ;
        #pragma unroll
        for (int it = 0; it < 4; ++it) {
            int j = tid + it * 256;
            int m = j >> 3, kq = j & 7;
            int off = m * ROWB + kq * 8;
            float4 xv = pxv[it], qv = pqv[it];
            float4 uv = make_float4(xv.x * qv.x, xv.y * qv.y, xv.z * qv.z, xv.w * qv.w);
            split_store(uv, base + 0 * A_TILE + off, base + 1 * A_TILE + off);
            split_store(xv, base + 2 * A_TILE + off, base + 3 * A_TILE + off);
            split_store(qv, base + 4 * A_TILE + off, base + 5 * A_TILE + off);
        }
    };
    auto stage_W = [&](int k0, int buf) {
        char* base = smem + buf * BUFSZ + 6 * A_TILE;
        int n = tid >> 2, s = tid & 3;
        #pragma unroll
        for (int m6 = 0; m6 < 6; ++m6) {
            uint4 v = *(const uint4*)(w6[m6] + (size_t)(nbase + n) * DD + k0 + s * 8);
            *(uint4*)(base + m6 * B_TILE + n * ROWB + s * 16) = v;
        }
    };

    // --- prologue: stage chunk 0 -------------------------------------------
    load_xq(0);
    stage_A(0);
    stage_W(0, 0);
    __syncthreads();

    // --- main loop ----------------------------------------------------------
    #pragma unroll 1
    for (int c = 0; c < NCHUNK; ++c) {
        if (c < NCHUNK - 1) load_xq((c + 1) * KC);  // gmem prefetch to regs

        const uint32_t abuf = sb + (c & 1) * BUFSZ;
        const uint32_t bbuf = abuf + 6 * A_TILE;
        const int r = lane & 7, g = lane >> 3;

        #pragma unroll
        for (int ks = 0; ks < 2; ++ks) {
            const uint32_t kso = ks * 32;
            // A fragments (U,X,Q hi then lo): [op3*2][mt][4]
            uint32_t af[6][2][4];
            #pragma unroll
            for (int o = 0; o < 6; ++o)
                #pragma unroll
                for (int mt = 0; mt < 2; ++mt) {
                    uint32_t addr = abuf + o * A_TILE
                        + (wm * 32 + mt * 16 + (g & 1) * 8 + r) * ROWB
                        + (g >> 1) * 16 + kso;
                    ldsm4(addr, af[o][mt]);
                }
            // B fragments: [mat6][nt4][2]
            uint32_t bf[6][4][2];
            #pragma unroll
            for (int m6 = 0; m6 < 6; ++m6)
                #pragma unroll
                for (int j = 0; j < 2; ++j) {
                    uint32_t tmp[4];
                    uint32_t addr = bbuf + m6 * B_TILE
                        + (wn * 32 + (2 * j + (g >> 1)) * 8 + r) * ROWB
                        + (g & 1) * 16 + kso;
                    ldsm4(addr, tmp);
                    bf[m6][2 * j][0] = tmp[0]; bf[m6][2 * j][1] = tmp[1];
                    bf[m6][2 * j + 1][0] = tmp[2]; bf[m6][2 * j + 1][1] = tmp[3];
                }
            // MMAs: hi*hi, hi*lo, lo*hi for each of (U->z), (X->h), (Q->h)
            #pragma unroll
            for (int mt = 0; mt < 2; ++mt)
                #pragma unroll
                for (int nt = 0; nt < 4; ++nt) {
                    mma16816(acc[0][mt][nt], af[0][mt], bf[0][nt]); // Uhi*Wzhi
                    mma16816(acc[0][mt][nt], af[0][mt], bf[1][nt]); // Uhi*Wzlo
                    mma16816(acc[0][mt][nt], af[1][mt], bf[0][nt]); // Ulo*Wzhi
                    mma16816(acc[1][mt][nt], af[2][mt], bf[2][nt]); // Xhi*Whxhi
                    mma16816(acc[1][mt][nt], af[2][mt], bf[3][nt]); // Xhi*Whxlo
                    mma16816(acc[1][mt][nt], af[3][mt], bf[2][nt]); // Xlo*Whxhi
                    mma16816(acc[1][mt][nt], af[4][mt], bf[4][nt]); // Qhi*Whqhi
                    mma16816(acc[1][mt][nt], af[4][mt], bf[5][nt]); // Qhi*Whqlo
                    mma16816(acc[1][mt][nt], af[5][mt], bf[4][nt]); // Qlo*Whqhi
                }
        }
        if (c < NCHUNK - 1) {
            stage_A((c + 1) & 1);
            stage_W((c + 1) * KC, (c + 1) & 1);
        }
        __syncthreads();
    }

    // --- epilogue: activations, smem transpose, coalesced stores -----------
    float* smA = (float*)smem;              // [128][68]
    float* smB = smA + 128 * 68;
    #pragma unroll
    for (int mt = 0; mt < 2; ++mt)
        #pragma unroll
        for (int nt = 0; nt < 4; ++nt) {
            int col = wn * 32 + nt * 8 + 2 * (lane & 3);
            int row0 = wm * 32 + mt * 16 + (lane >> 2);
            #pragma unroll
            for (int h8 = 0; h8 < 2; ++h8) {
                int row = row0 + h8 * 8;
                float z0 = 0.5f * tanh_fast(0.5f * (acc[0][mt][nt][2*h8+0] + bzs[col]))   + 0.5f;
                float z1 = 0.5f * tanh_fast(0.5f * (acc[0][mt][nt][2*h8+1] + bzs[col+1])) + 0.5f;
                float t0 = tanh_fast(acc[1][mt][nt][2*h8+0] + bhs[col]);
                float t1 = tanh_fast(acc[1][mt][nt][2*h8+1] + bhs[col+1]);
                float2 av = make_float2(1.f - z0, 1.f - z1);
                float2 bv = make_float2(z0 * t0, z1 * t1);
                *(float2*)(smA + row * 68 + col) = av;
                *(float2*)(smB + row * 68 + col) = bv;
            }
        }
    __syncthreads();
    #pragma unroll
    for (int it = 0; it < 8; ++it) {
        int j = tid + it * 256;
        int row = j >> 4, cf = j & 15;
        size_t go = (size_t)(tbase + row) * DD + nbase + cf * 4;
        *(float4*)(outA + go) = *(const float4*)(smA + row * 68 + cf * 4);
        *(float4*)(outB + go) = *(const float4*)(smB + row * 68 + cf * 4);
    }
}

// ---------------------------------------------------------------------------
// scan1: block-local scan, in place; emits per-block aggregate.
// ---------------------------------------------------------------------------
__global__ void scan1_kernel(float* __restrict__ A, float* __restrict__ B,
                             float* __restrict__ aggA, float* __restrict__ aggB)
{
    const int d = threadIdx.x;
    const int base = blockIdx.x * CS * DD + d;
    float Ap = 1.f, hl = 0.f;
    for (int i0 = 0; i0 < CS; i0 += 8) {
        float a[8], bb[8];
        #pragma unroll
        for (int i = 0; i < 8; ++i) {
            a[i]  = A[base + (i0 + i) * DD];
            bb[i] = B[base + (i0 + i) * DD];
        }
        #pragma unroll
        for (int i = 0; i < 8; ++i) {
            Ap *= a[i];
            hl = fmaf(a[i], hl, bb[i]);
            a[i] = Ap;
            bb[i] = hl;
        }
        #pragma unroll
        for (int i = 0; i < 8; ++i) {
            A[base + (i0 + i) * DD] = a[i];
            B[base + (i0 + i) * DD] = bb[i];
        }
    }
    aggA[blockIdx.x * DD + d] = Ap;
    aggB[blockIdx.x * DD + d] = hl;
}

__global__ void scan2_kernel(const float* __restrict__ aggA,
                             const float* __restrict__ aggB,
                             float* __restrict__ hex)
{
    const int d = threadIdx.x;
    float H = 0.f;
    for (int b = 0; b < NB; ++b) {
        hex[b * DD + d] = H;
        H = fmaf(aggA[b * DD + d], H, aggB[b * DD + d]);
    }
}

__global__ void combine_kernel(
    const float* __restrict__ Af, const float* __restrict__ Bf,
    const float* __restrict__ hexf,
    const float* __restrict__ Ab, const float* __restrict__ Bb,
    const float* __restrict__ hexb,
    float* __restrict__ qout)
{
    int idx = blockIdx.x * blockDim.x + threadIdx.x;
    int t = idx >> 6;
    int c = (idx & 63) << 2;
    int tr = TT - 1 - t;
    int blf = t >> 8;
    int blb = tr >> 8;

    float4 af = *(const float4*)(Af + t * DD + c);
    float4 bf = *(const float4*)(Bf + t * DD + c);
    float4 hf = *(const float4*)(hexf + blf * DD + c);
    float4 ab = *(const float4*)(Ab + tr * DD + c);
    float4 bb = *(const float4*)(Bb + tr * DD + c);
    float4 hb = *(const float4*)(hexb + blb * DD + c);

    float4 o;
    o.x = fmaf(af.x, hf.x, bf.x) + fmaf(ab.x, hb.x, bb.x);
    o.y = fmaf(af.y, hf.y, bf.y) + fmaf(ab.y, hb.y, bb.y);
    o.z = fmaf(af.z, hf.z, bf.z) + fmaf(ab.z, hb.z, bb.z);
    o.w = fmaf(af.w, hf.w, bf.w) + fmaf(ab.w, hb.w, bb.w);
    *(float4*)(qout + t * DD + c) = o;
}

__global__ void final_kernel(const float* __restrict__ Af,
                             const float* __restrict__ Bf,
                             const float* __restrict__ hexf,
                             float* __restrict__ out)
{
    const int d = threadIdx.x;
    out[d] = fmaf(Af[(TT - 1) * DD + d], hexf[(NB - 1) * DD + d],
                  Bf[(TT - 1) * DD + d]);
}

// ---------------------------------------------------------------------------
// Host orchestration
// ---------------------------------------------------------------------------
extern "C" void kernel_launch(void* const* d_in, const int* in_sizes, int n_in,
                              void* d_out, int out_size)
{
    const float* story    = (const float*)d_in[0];
    const float* question = (const float*)d_in[1];
    const float* Wz_f = (const float*)d_in[2];
    const float* bz_f = (const float*)d_in[3];
    const float* Wh_f = (const float*)d_in[4];
    const float* bh_f = (const float*)d_in[5];
    const float* Wz_b = (const float*)d_in[6];
    const float* bz_b = (const float*)d_in[7];
    const float* Wh_b = (const float*)d_in[8];
    const float* bh_b = (const float*)d_in[9];
    float* out = (float*)d_out;

    float *qbuf, *af, *bf, *ab, *bb;
    float *aggAf, *aggBf, *hexf, *aggAb, *aggBb, *hexb;
    __nv_bfloat16 *whi, *wlo;
    cudaGetSymbolAddress((void**)&qbuf,  g_q);
    cudaGetSymbolAddress((void**)&af,    g_af);
    cudaGetSymbolAddress((void**)&bf,    g_bf);
    cudaGetSymbolAddress((void**)&ab,    g_ab);
    cudaGetSymbolAddress((void**)&bb,    g_bb);
    cudaGetSymbolAddress((void**)&aggAf, g_aggA_f);
    cudaGetSymbolAddress((void**)&aggBf, g_aggB_f);
    cudaGetSymbolAddress((void**)&hexf,  g_hex_f);
    cudaGetSymbolAddress((void**)&aggAb, g_aggA_b);
    cudaGetSymbolAddress((void**)&aggBb, g_aggB_b);
    cudaGetSymbolAddress((void**)&hexb,  g_hex_b);
    cudaGetSymbolAddress((void**)&whi,   g_whi);
    cudaGetSymbolAddress((void**)&wlo,   g_wlo);

    static int smem_set = 0;
    if (!smem_set) {
        cudaFuncSetAttribute(gemm_mma, cudaFuncAttributeMaxDynamicSharedMemorySize,
                             SMEM_TOTAL);
        smem_set = 1;
    }

    // Preprocess weights: slots 0..2 = fwd L0..L2, 3..4 = bwd L0..L1
    const int MSZ = 3 * DD * DD;
    for (int l = 0; l < LL; ++l)
        prep_weights<<<dim3(DD, 3), 256>>>(Wz_f + l * DD * DD, Wh_f + l * 2 * DD * DD,
                                           whi + l * MSZ, wlo + l * MSZ);
    for (int l = 0; l < LL - 1; ++l)
        prep_weights<<<dim3(DD, 3), 256>>>(Wz_b + l * DD * DD, Wh_b + l * 2 * DD * DD,
                                           whi + (3 + l) * MSZ, wlo + (3 + l) * MSZ);

    dim3 ggrid(TT / BM, DD / BN);  // (512, 4)

    for (int l = 0; l < LL; ++l) {
        const float* qp = (l == 0) ? question : qbuf;
        int qstride = (l == 0) ? 0 : DD;

        // forward direction
        gemm_mma<<<ggrid, 256, SMEM_TOTAL>>>(
            story, qp, qstride, 0,
            whi + l * MSZ, wlo + l * MSZ,
            bz_f + l * DD, bh_f + l * DD, af, bf);
        scan1_kernel<<<NB, 256>>>(af, bf, aggAf, aggBf);
        scan2_kernel<<<1, 256>>>(aggAf, aggBf, hexf);

        if (l < LL - 1) {
            // backward direction (last layer's backward is dead code)
            gemm_mma<<<ggrid, 256, SMEM_TOTAL>>>(
                story, qp, qstride, 1,
                whi + (3 + l) * MSZ, wlo + (3 + l) * MSZ,
                bz_b + l * DD, bh_b + l * DD, ab, bb);
            scan1_kernel<<<NB, 256>>>(ab, bb, aggAb, aggBb);
            scan2_kernel<<<1, 256>>>(aggAb, aggBb, hexb);

            combine_kernel<<<TT * DD / 4 / 256, 256>>>(
                af, bf, hexf, ab, bb, hexb, qbuf);
        } else {
            final_kernel<<<1, 256>>>(af, bf, hexf, out);
        }
    }
}